// round 9
// baseline (speedup 1.0000x reference)
#include <cuda_runtime.h>

#define THREADS 256
#define TB 16
#define XPAD 2080                 // per-batch row block: 64*32 + 32 pad
#define XBUF (TB * XPAD)          // 33280 bytes
#define WBYTES 131072             // packed weights for one n-half (both tensors)
#define SMEM_BYTES (WBYTES + 2 * XBUF)   // 197632

typedef unsigned long long ull;

__device__ __forceinline__ void unpk(ull v, float& lo, float& hi) {
    asm("mov.b64 {%0, %1}, %2;" : "=f"(lo), "=f"(hi) : "l"(v));
}
__device__ __forceinline__ ull ffma2(ull a, ull b, ull c) {
    ull d;
    asm("fma.rn.f32x2 %0, %1, %2, %3;" : "=l"(d) : "l"(a), "l"(b), "l"(c));
    return d;
}

// ---------------------------------------------------------------------------
// stage one x tile (16 batches = 32KB) into smem as [b][m][8] floats with
// per-batch row block of XPAD=2080 bytes (2048 data + 32 pad).
// dst for float4 index i = i*16 + (i>>7)*32 ; with i = tid + r*256 this is
// (tid*16 + (tid>>7)*32) + r*4160  -> pure immediate stride, zero ALU.
// ---------------------------------------------------------------------------
__device__ __forceinline__ void stage_tile(const float* __restrict__ x,
                                           char* dstbase, int tile,
                                           int tid, unsigned int xsb) {
    const float4* src = reinterpret_cast<const float4*>(x) + (size_t)tile * 2048 + tid;
    unsigned int ds = (unsigned int)__cvta_generic_to_shared(dstbase) + xsb;
#pragma unroll
    for (int r = 0; r < 8; r++) {
        asm volatile("cp.async.cg.shared.global [%0], [%1], 16;\n"
                     :: "r"(ds + r * 4160), "l"(src + r * 256));
    }
    asm volatile("cp.async.commit_group;\n");
}

__global__ __launch_bounds__(THREADS, 1)
void clifford_gate_kernel(const float* __restrict__ x,
                          const float* __restrict__ wp,
                          const float* __restrict__ bpr,
                          const float* __restrict__ wm,
                          const float* __restrict__ bmr,
                          float* __restrict__ out,
                          int ntiles) {
    extern __shared__ char smc[];
    char* wsm = smc;                 // packed weights, 128KB
    char* xb  = smc + WBYTES;        // 2 x XBUF

    const int tid  = threadIdx.x;
    const int lane = tid & 31;
    const int warp = tid >> 5;
    const int l8 = lane & 7;         // n within oct
    const int k  = lane >> 3;        // batch sub-slot 0..3
    const int o  = warp & 3;         // n oct 0..3
    const int g  = warp >> 2;        // batch group 0/1 -> b = g*8 + k + 4j
    const int h  = blockIdx.x & 1;   // n half
    const int n  = h * 32 + o * 8 + l8;

    // ---- prepack weights for this n-half into smem, once ----
    // layout (float4 units): [m][oct][chunk0..3][l8]
    //   chunk0 = (p.x, p.y, p.y, p.y)   -> packs AB=(w0,w1), BB=(w1,w1) (probe)
    //   chunk1 = (p.z, p.z, p.z, p.w)   -> packs CC=(w2,w2), CD=(w2,w3) (probe)
    //   chunk2, chunk3 = same for match
    {
        const float4* gp = reinterpret_cast<const float4*>(wp);
        const float4* gm = reinterpret_cast<const float4*>(wm);
        float4* wv = reinterpret_cast<float4*>(wsm);
        for (int idx = tid; idx < 2048; idx += THREADS) {
            int m = idx >> 5, nn = idx & 31;
            int oo = nn >> 3, ll = nn & 7;
            float4 a = gp[(h * 32 + nn) * 64 + m];
            float4 c = gm[(h * 32 + nn) * 64 + m];
            int base = ((m * 4 + oo) * 4) * 8 + ll;
            wv[base     ] = make_float4(a.x, a.y, a.y, a.y);
            wv[base + 8 ] = make_float4(a.z, a.z, a.z, a.w);
            wv[base + 16] = make_float4(c.x, c.y, c.y, c.y);
            wv[base + 24] = make_float4(c.z, c.z, c.z, c.w);
        }
    }
    const float biasp = bpr[n];
    const float biasm = bmr[n];

    const unsigned int xsb = (unsigned int)(tid * 16 + (tid >> 7) * 32);
    const char* wb = wsm + o * 512 + l8 * 16;   // + m*2048 + chunk*128
    const int xoff = (g * 8 + k) * XPAD;        // j adds 4*XPAD

    int t = blockIdx.x >> 1;
    const int stride = gridDim.x >> 1;
    if (t < ntiles) stage_tile(x, xb, t, tid, xsb);
    asm volatile("cp.async.wait_group 0;\n");
    __syncthreads();

    int cur = 0;
    const float s2 = 0.70710678118654752440f;

    for (; t < ntiles; t += stride) {
        int tn = t + stride;
        if (tn < ntiles) stage_tile(x, xb + (cur ^ 1) * XBUF, tn, tid, xsb);

        // ---------------- mainloop ----------------
        // Per-blade reduction: single accumulator, m ascending, fused fma —
        // DO NOT change (bit-exact vs reference; gate/q are singular).
        ull aP[2][4], aM[2][4];
#pragma unroll
        for (int i = 0; i < 2; i++)
#pragma unroll
            for (int j = 0; j < 4; j++) { aP[i][j] = 0ull; aM[i][j] = 0ull; }

        const char* x0 = xb + cur * XBUF + xoff;     // j=0
        const char* x1 = x0 + 4 * XPAD;              // j=1

#pragma unroll 4
        for (int m = 0; m < 64; m++) {
            const char* wr = wb + m * 2048;
            ulonglong2 pA = *reinterpret_cast<const ulonglong2*>(wr);        // AB,BB
            ulonglong2 pB = *reinterpret_cast<const ulonglong2*>(wr + 128);  // CC,CD
            ulonglong2 mA = *reinterpret_cast<const ulonglong2*>(wr + 256);
            ulonglong2 mB = *reinterpret_cast<const ulonglong2*>(wr + 384);

            ulonglong2 c00 = *reinterpret_cast<const ulonglong2*>(x0 + m * 32);
            ulonglong2 c01 = *reinterpret_cast<const ulonglong2*>(x0 + m * 32 + 16);
            ulonglong2 c10 = *reinterpret_cast<const ulonglong2*>(x1 + m * 32);
            ulonglong2 c11 = *reinterpret_cast<const ulonglong2*>(x1 + m * 32 + 16);

            aP[0][0] = ffma2(c00.x, pA.x, aP[0][0]);   // blades 0,1
            aP[0][1] = ffma2(c00.y, pA.y, aP[0][1]);   // blades 2,3
            aP[0][2] = ffma2(c01.x, pB.x, aP[0][2]);   // blades 4,5
            aP[0][3] = ffma2(c01.y, pB.y, aP[0][3]);   // blades 6,7
            aM[0][0] = ffma2(c00.x, mA.x, aM[0][0]);
            aM[0][1] = ffma2(c00.y, mA.y, aM[0][1]);
            aM[0][2] = ffma2(c01.x, mB.x, aM[0][2]);
            aM[0][3] = ffma2(c01.y, mB.y, aM[0][3]);

            aP[1][0] = ffma2(c10.x, pA.x, aP[1][0]);
            aP[1][1] = ffma2(c10.y, pA.y, aP[1][1]);
            aP[1][2] = ffma2(c11.x, pB.x, aP[1][2]);
            aP[1][3] = ffma2(c11.y, pB.y, aP[1][3]);
            aM[1][0] = ffma2(c10.x, mA.x, aM[1][0]);
            aM[1][1] = ffma2(c10.y, mA.y, aM[1][1]);
            aM[1][2] = ffma2(c11.x, mB.x, aM[1][2]);
            aM[1][3] = ffma2(c11.y, mB.y, aM[1][3]);
        }

        // ---------------- epilogue ----------------
#pragma unroll
        for (int j = 0; j < 2; j++) {
            float p0, p1, p2, p3, p4, p5, p6, p7;
            float m0, m1, m2, m3, m4, m5, m6, m7;
            unpk(aP[j][0], p0, p1); unpk(aP[j][1], p2, p3);
            unpk(aP[j][2], p4, p5); unpk(aP[j][3], p6, p7);
            unpk(aM[j][0], m0, m1); unpk(aM[j][1], m2, m3);
            unpk(aM[j][2], m4, m5); unpk(aM[j][3], m6, m7);
            p0 = __fadd_rn(p0, biasp);
            m0 = __fadd_rn(m0, biasm);

            // gate: individually rounded multiplies + sequential adds i=0..7.
            // NO FMA here (bit-exactness near b==0 is required).
            float bgv;
            bgv = __fmul_rn(p0, m0);
            bgv = __fadd_rn(bgv, __fmul_rn(p1, m1));
            bgv = __fadd_rn(bgv, __fmul_rn(p2, m2));
            bgv = __fadd_rn(bgv, __fmul_rn(p3, m3));
            bgv = __fadd_rn(bgv, __fmul_rn(p4, m4));
            bgv = __fadd_rn(bgv, __fmul_rn(p5, m5));
            bgv = __fadd_rn(bgv, __fmul_rn(p6, m6));
            bgv = __fadd_rn(bgv, __fmul_rn(p7, m7));

            // q: same rounding discipline (singular near q==0).
            float qv;
            qv = __fmul_rn(m0, m0);
            qv = __fadd_rn(qv, __fmul_rn(m1, m1));
            qv = __fadd_rn(qv, __fmul_rn(m2, m2));
            qv = __fadd_rn(qv, __fmul_rn(m3, m3));
            qv = __fadd_rn(qv, -__fmul_rn(m4, m4));
            qv = __fadd_rn(qv, -__fmul_rn(m5, m5));
            qv = __fadd_rn(qv, -__fmul_rn(m6, m6));
            qv = __fadd_rn(qv, -__fmul_rn(m7, m7));

            float qs  = __fadd_rn(__fmul_rn(qv, qv), 1e-16f);
            float nrm = __fsqrt_rn(__fsqrt_rn(qs));
            float inv = __frcp_rn(nrm);

            float n0 = m0 * inv, n1 = m1 * inv, n2 = m2 * inv, n3 = m3 * inv;
            float n4 = m4 * inv, n5 = m5 * inv, n6 = m6 * inv, n7 = m7 * inv;

            // Cl(3,0) geometric product r = p * n (well-conditioned; fma ok)
            float r0 = p0*n0 + p1*n1 + p2*n2 + p3*n3 - p4*n4 - p5*n5 - p6*n6 - p7*n7;
            float r1 = p0*n1 + p1*n0 - p2*n4 + p4*n2 - p3*n5 + p5*n3 - p6*n7 - p7*n6;
            float r2 = p0*n2 + p2*n0 + p1*n4 - p4*n1 - p3*n6 + p6*n3 + p5*n7 + p7*n5;
            float r3 = p0*n3 + p3*n0 + p1*n5 - p5*n1 + p2*n6 - p6*n2 - p4*n7 - p7*n4;
            float r4 = p0*n4 + p4*n0 + p1*n2 - p2*n1 + p3*n7 + p7*n3 - p5*n6 + p6*n5;
            float r5 = p0*n5 + p5*n0 + p1*n3 - p3*n1 - p2*n7 - p7*n2 + p4*n6 - p6*n4;
            float r6 = p0*n6 + p6*n0 + p1*n7 + p7*n1 + p2*n3 - p3*n2 - p4*n5 + p5*n4;
            float r7 = p0*n7 + p7*n0 + p1*n6 + p6*n1 - p2*n5 - p5*n2 + p3*n4 + p4*n3;

            bool sel = bgv > 0.0f;
            float4 o0, o1;
            o0.x = (sel ? p0 : r0) * s2;
            o0.y = (sel ? p1 : r1) * s2;
            o0.z = (sel ? p2 : r2) * s2;
            o0.w = (sel ? p3 : r3) * s2;
            o1.x = (sel ? p4 : r4) * s2;
            o1.y = (sel ? p5 : r5) * s2;
            o1.z = (sel ? p6 : r6) * s2;
            o1.w = (sel ? p7 : r7) * s2;

            size_t brow = (size_t)t * TB + (size_t)(g * 8 + k + 4 * j);
            float4* op = reinterpret_cast<float4*>(out + ((brow << 6) + n) * 8);
            op[0] = o0;
            op[1] = o1;
        }

        asm volatile("cp.async.wait_group 0;\n");
        __syncthreads();
        cur ^= 1;
    }
}

extern "C" void kernel_launch(void* const* d_in, const int* in_sizes, int n_in,
                              void* d_out, int out_size) {
    const float* x   = (const float*)d_in[0];
    const float* wp  = (const float*)d_in[1];
    const float* bpr = (const float*)d_in[2];
    const float* wm  = (const float*)d_in[3];
    const float* bmr = (const float*)d_in[4];
    float* out = (float*)d_out;

    int B = in_sizes[0] / 512;      // x is (B, 64, 8)
    int ntiles = B / TB;

    cudaFuncSetAttribute(clifford_gate_kernel,
                         cudaFuncAttributeMaxDynamicSharedMemorySize, SMEM_BYTES);

    int dev = 0, sms = 148;
    cudaGetDevice(&dev);
    cudaDeviceGetAttribute(&sms, cudaDevAttrMultiProcessorCount, dev);
    int half = sms < ntiles ? sms : ntiles;
    if (half < 1) half = 1;
    int grid = 2 * half;            // bid&1 = n-half, bid>>1 = tile start

    clifford_gate_kernel<<<grid, THREADS, SMEM_BYTES>>>(
        x, wp, bpr, wm, bmr, out, ntiles);
}

// round 10
// speedup vs baseline: 1.2689x; 1.2689x over previous
#include <cuda_runtime.h>

#define THREADS 256
#define TB 32
#define HBYTES 32768                       // half tile: 16 batches x 2048B
#define WBYTES 131072                      // weights [m][n][4] x 2 tensors
#define SMEM_BYTES (WBYTES + 3 * HBYTES)   // 229376

typedef unsigned long long ull;

__device__ __forceinline__ ull pk2(float lo, float hi) {
    ull r;
    asm("mov.b64 %0, {%1, %2};" : "=l"(r) : "f"(lo), "f"(hi));
    return r;
}
__device__ __forceinline__ void unpk(ull v, float& lo, float& hi) {
    asm("mov.b64 {%0, %1}, %2;" : "=f"(lo), "=f"(hi) : "l"(v));
}
__device__ __forceinline__ ull ffma2(ull a, ull b, ull c) {
    ull d;
    asm("fma.rn.f32x2 %0, %1, %2, %3;" : "=l"(d) : "l"(a), "l"(b), "l"(c));
    return d;
}

#define WAITG0() asm volatile("cp.async.wait_group 0;\n")
#define WAITG1() asm volatile("cp.async.wait_group 1;\n")

// stage 16 batches (32KB) starting at global batch b0 into one slot, layout
// [b][m][8] natural (2048B per batch). One commit group.
__device__ __forceinline__ void stage_half(const float* __restrict__ x,
                                           char* slot, long long b0, int tid) {
    const float4* src = reinterpret_cast<const float4*>(x) + b0 * 128 + tid;
    unsigned int ds = (unsigned int)__cvta_generic_to_shared(slot) + tid * 16;
#pragma unroll
    for (int r = 0; r < 8; r++) {
        asm volatile("cp.async.cg.shared.global [%0], [%1], 16;\n"
                     :: "r"(ds + r * 4096), "l"(src + r * 256));
    }
    asm volatile("cp.async.commit_group;\n");
}

__global__ __launch_bounds__(THREADS, 1)
void clifford_gate_kernel(const float* __restrict__ x,
                          const float* __restrict__ wp,
                          const float* __restrict__ bpr,
                          const float* __restrict__ wm,
                          const float* __restrict__ bmr,
                          float* __restrict__ out,
                          int ntiles) {
    extern __shared__ char smc[];
    float4* wsp = reinterpret_cast<float4*>(smc);            // [m*64+n] probe
    float4* wsm = wsp + 4096;                                 // [m*64+n] match
    char* xs0 = smc + WBYTES;
    char* xs1 = xs0 + HBYTES;
    char* xs2 = xs1 + HBYTES;

    const int tid  = threadIdx.x;
    const int lane = tid & 31;
    const int warp = tid >> 5;
    const int n = ((warp & 1) << 5) | lane;   // 0..63
    const int g = warp >> 1;                  // batch group 0..3: b = g*8 + j

    // ---- stage weights once: gmem [n][m][4] -> smem [m][n][4] ----
    {
        const float4* gp = reinterpret_cast<const float4*>(wp);
        const float4* gm = reinterpret_cast<const float4*>(wm);
        for (int idx = tid; idx < 4096; idx += THREADS) {
            int nn = idx & 63, mm = idx >> 6;
            wsp[mm * 64 + nn] = gp[nn * 64 + mm];
            wsm[mm * 64 + nn] = gm[nn * 64 + mm];
        }
    }
    const float biasp = bpr[n];
    const float biasm = bmr[n];

    int t = blockIdx.x;
    const int stride = gridDim.x;

    char* slots[3] = {xs0, xs1, xs2};
    int s0 = 0, s1 = 1;

    if (t < ntiles) {
        stage_half(x, xs0, (long long)t * TB, tid);
        stage_half(x, xs1, (long long)t * TB + 16, tid);
    }
    WAITG0();
    __syncthreads();

    const float s2c = 0.70710678118654752440f;
    const int goff = (g & 1) * 16384;   // batch-in-half offset (8 batches)

    for (; t < ntiles; t += stride) {
        int tn = t + stride;
        int sA = s0 + 2; if (sA >= 3) sA -= 3;   // slot for next tile's half 0

        if (tn < ntiles) {
            stage_half(x, slots[sA], (long long)tn * TB, tid);
            WAITG1();      // current tile's two halves complete
        } else {
            WAITG0();
        }
        __syncthreads();

        // ---------------- mainloop ----------------
        // Per-blade reduction: single accumulator, m ascending, fused fma —
        // DO NOT change (bit-exact vs reference; gate/q are singular).
        ull aP[8][4], aM[8][4];
#pragma unroll
        for (int j = 0; j < 8; j++)
#pragma unroll
            for (int i = 0; i < 4; i++) { aP[j][i] = 0ull; aM[j][i] = 0ull; }

        const char* xg = (g < 2 ? slots[s0] : slots[s1]) + goff;

#pragma unroll 2
        for (int m = 0; m < 64; m++) {
            float4 wpv = wsp[(m << 6) + n];
            float4 wmv = wsm[(m << 6) + n];
            // packs: A=(w0,w1), D=(w2,w3) free halves; B=(w1,w1), C=(w2,w2)
            ull wpA, wpD, wmA, wmD;
            {
                const ulonglong2* u = reinterpret_cast<const ulonglong2*>(&wpv);
                wpA = u->x; wpD = u->y;
                const ulonglong2* v = reinterpret_cast<const ulonglong2*>(&wmv);
                wmA = v->x; wmD = v->y;
            }
            ull wpB = pk2(wpv.y, wpv.y), wpC = pk2(wpv.z, wpv.z);
            ull wmB = pk2(wmv.y, wmv.y), wmC = pk2(wmv.z, wmv.z);

            const char* xr = xg + m * 32;
#pragma unroll
            for (int j = 0; j < 8; j++) {
                ulonglong2 c0 = *reinterpret_cast<const ulonglong2*>(xr + j * 2048);
                ulonglong2 c1 = *reinterpret_cast<const ulonglong2*>(xr + j * 2048 + 16);
                aP[j][0] = ffma2(c0.x, wpA, aP[j][0]);   // blades 0,1
                aP[j][1] = ffma2(c0.y, wpB, aP[j][1]);   // blades 2,3
                aP[j][2] = ffma2(c1.x, wpC, aP[j][2]);   // blades 4,5
                aP[j][3] = ffma2(c1.y, wpD, aP[j][3]);   // blades 6,7
                aM[j][0] = ffma2(c0.x, wmA, aM[j][0]);
                aM[j][1] = ffma2(c0.y, wmB, aM[j][1]);
                aM[j][2] = ffma2(c1.x, wmC, aM[j][2]);
                aM[j][3] = ffma2(c1.y, wmD, aM[j][3]);
            }
        }

        // ---------------- epilogue ----------------
#pragma unroll
        for (int j = 0; j < 8; j++) {
            float p0, p1, p2, p3, p4, p5, p6, p7;
            float m0, m1, m2, m3, m4, m5, m6, m7;
            unpk(aP[j][0], p0, p1); unpk(aP[j][1], p2, p3);
            unpk(aP[j][2], p4, p5); unpk(aP[j][3], p6, p7);
            unpk(aM[j][0], m0, m1); unpk(aM[j][1], m2, m3);
            unpk(aM[j][2], m4, m5); unpk(aM[j][3], m6, m7);
            p0 = __fadd_rn(p0, biasp);
            m0 = __fadd_rn(m0, biasm);

            // gate: individually rounded multiplies + sequential adds i=0..7.
            // NO FMA here (bit-exactness near b==0 is required).
            float bgv;
            bgv = __fmul_rn(p0, m0);
            bgv = __fadd_rn(bgv, __fmul_rn(p1, m1));
            bgv = __fadd_rn(bgv, __fmul_rn(p2, m2));
            bgv = __fadd_rn(bgv, __fmul_rn(p3, m3));
            bgv = __fadd_rn(bgv, __fmul_rn(p4, m4));
            bgv = __fadd_rn(bgv, __fmul_rn(p5, m5));
            bgv = __fadd_rn(bgv, __fmul_rn(p6, m6));
            bgv = __fadd_rn(bgv, __fmul_rn(p7, m7));

            // q: same rounding discipline (singular near q==0).
            float qv;
            qv = __fmul_rn(m0, m0);
            qv = __fadd_rn(qv, __fmul_rn(m1, m1));
            qv = __fadd_rn(qv, __fmul_rn(m2, m2));
            qv = __fadd_rn(qv, __fmul_rn(m3, m3));
            qv = __fadd_rn(qv, -__fmul_rn(m4, m4));
            qv = __fadd_rn(qv, -__fmul_rn(m5, m5));
            qv = __fadd_rn(qv, -__fmul_rn(m6, m6));
            qv = __fadd_rn(qv, -__fmul_rn(m7, m7));

            float qs  = __fadd_rn(__fmul_rn(qv, qv), 1e-16f);
            float nrm = __fsqrt_rn(__fsqrt_rn(qs));
            float inv = __frcp_rn(nrm);

            float n0 = m0 * inv, n1 = m1 * inv, n2 = m2 * inv, n3 = m3 * inv;
            float n4 = m4 * inv, n5 = m5 * inv, n6 = m6 * inv, n7 = m7 * inv;

            // Cl(3,0) geometric product r = p * n (well-conditioned; fma ok)
            float r0 = p0*n0 + p1*n1 + p2*n2 + p3*n3 - p4*n4 - p5*n5 - p6*n6 - p7*n7;
            float r1 = p0*n1 + p1*n0 - p2*n4 + p4*n2 - p3*n5 + p5*n3 - p6*n7 - p7*n6;
            float r2 = p0*n2 + p2*n0 + p1*n4 - p4*n1 - p3*n6 + p6*n3 + p5*n7 + p7*n5;
            float r3 = p0*n3 + p3*n0 + p1*n5 - p5*n1 + p2*n6 - p6*n2 - p4*n7 - p7*n4;
            float r4 = p0*n4 + p4*n0 + p1*n2 - p2*n1 + p3*n7 + p7*n3 - p5*n6 + p6*n5;
            float r5 = p0*n5 + p5*n0 + p1*n3 - p3*n1 - p2*n7 - p7*n2 + p4*n6 - p6*n4;
            float r6 = p0*n6 + p6*n0 + p1*n7 + p7*n1 + p2*n3 - p3*n2 - p4*n5 + p5*n4;
            float r7 = p0*n7 + p7*n0 + p1*n6 + p6*n1 - p2*n5 - p5*n2 + p3*n4 + p4*n3;

            bool sel = bgv > 0.0f;
            float4 o0, o1;
            o0.x = (sel ? p0 : r0) * s2c;
            o0.y = (sel ? p1 : r1) * s2c;
            o0.z = (sel ? p2 : r2) * s2c;
            o0.w = (sel ? p3 : r3) * s2c;
            o1.x = (sel ? p4 : r4) * s2c;
            o1.y = (sel ? p5 : r5) * s2c;
            o1.z = (sel ? p6 : r6) * s2c;
            o1.w = (sel ? p7 : r7) * s2c;

            size_t brow = (size_t)t * TB + (size_t)(g * 8 + j);
            float4* op = reinterpret_cast<float4*>(out + ((brow << 6) + n) * 8);
            op[0] = o0;
            op[1] = o1;
        }

        __syncthreads();
        if (tn < ntiles) {
            // stage next tile's half 1 into the slot just freed (s0)
            stage_half(x, slots[s0], (long long)tn * TB + 16, tid);
        }
        // rotate slots: next (s0, s1) = (sA, s0)
        s1 = s0;
        s0 = sA;
    }
}

extern "C" void kernel_launch(void* const* d_in, const int* in_sizes, int n_in,
                              void* d_out, int out_size) {
    const float* x   = (const float*)d_in[0];
    const float* wp  = (const float*)d_in[1];
    const float* bpr = (const float*)d_in[2];
    const float* wm  = (const float*)d_in[3];
    const float* bmr = (const float*)d_in[4];
    float* out = (float*)d_out;

    int B = in_sizes[0] / 512;      // x is (B, 64, 8)
    int ntiles = B / TB;

    cudaFuncSetAttribute(clifford_gate_kernel,
                         cudaFuncAttributeMaxDynamicSharedMemorySize, SMEM_BYTES);

    int dev = 0, sms = 148;
    cudaGetDevice(&dev);
    cudaDeviceGetAttribute(&sms, cudaDevAttrMultiProcessorCount, dev);
    int grid = sms < ntiles ? sms : ntiles;
    if (grid < 1) grid = 1;

    clifford_gate_kernel<<<grid, THREADS, SMEM_BYTES>>>(
        x, wp, bpr, wm, bmr, out, ntiles);
}

// round 11
// speedup vs baseline: 1.8302x; 1.4423x over previous
#include <cuda_runtime.h>

#define THREADS 256
#define TB 16
// smem: wp [m][n][4] 64KB + wm 64KB + 2 x-buffers of 32KB = 192KB
#define SMEM_BYTES 196608

typedef unsigned long long ull;

__device__ __forceinline__ ull pk2(float lo, float hi) {
    ull r;
    asm("mov.b64 %0, {%1, %2};" : "=l"(r) : "f"(lo), "f"(hi));
    return r;
}
__device__ __forceinline__ void unpk(ull v, float& lo, float& hi) {
    asm("mov.b64 {%0, %1}, %2;" : "=f"(lo), "=f"(hi) : "l"(v));
}
__device__ __forceinline__ ull ffma2(ull a, ull b, ull c) {
    ull d;
    asm("fma.rn.f32x2 %0, %1, %2, %3;" : "=l"(d) : "l"(a), "l"(b), "l"(c));
    return d;
}

// stage one tile (TB batches = TB*64*8 floats = 32KB, contiguous) into smem
__device__ __forceinline__ void stage_tile(const float* __restrict__ x,
                                           float* dst, int tile, int tid) {
    const float4* src = reinterpret_cast<const float4*>(x) + (size_t)tile * (TB * 128);
    float4* d4 = reinterpret_cast<float4*>(dst);
#pragma unroll
    for (int k = 0; k < 8; k++) {
        int i = tid + k * THREADS;
        unsigned int ds = (unsigned int)__cvta_generic_to_shared(d4 + i);
        asm volatile("cp.async.cg.shared.global [%0], [%1], 16;\n"
                     :: "r"(ds), "l"(src + i));
    }
    asm volatile("cp.async.commit_group;\n");
}

// ---- pipeline stage helpers (keep loads / math separable for ptxas) ----
__device__ __forceinline__ void ldw(const float4* __restrict__ wsp,
                                    const float4* __restrict__ wsm,
                                    int m, int n, float4& wpv, float4& wmv) {
    wpv = wsp[(m << 6) + n];
    wmv = wsm[(m << 6) + n];
}

__device__ __forceinline__ void ldx(const float* __restrict__ xbc,
                                    int bg4, int m,
                                    ulonglong2* c0, ulonglong2* c1) {
#pragma unroll
    for (int bb = 0; bb < 4; bb++) {
        const ulonglong2* xp = reinterpret_cast<const ulonglong2*>(
            xbc + (((bg4 + bb) << 6) + m) * 8);
        c0[bb] = xp[0];
        c1[bb] = xp[1];
    }
}

// one m-step of both GEMMs: per-blade single-accumulator fused-fma chains,
// m ascending — DO NOT change (bit-exact vs reference; gate/q are singular).
__device__ __forceinline__ void domma(const float4& wpv, const float4& wmv,
                                      const ulonglong2* c0, const ulonglong2* c1,
                                      ull aP[4][4], ull aM[4][4]) {
    // SUBSPACE packs: A=(w0,w1), B=(w1,w1), C=(w2,w2), D=(w2,w3)
    ull wpA, wpD, wmA, wmD;
    {
        const ulonglong2* u = reinterpret_cast<const ulonglong2*>(&wpv);
        wpA = u->x; wpD = u->y;
        const ulonglong2* v = reinterpret_cast<const ulonglong2*>(&wmv);
        wmA = v->x; wmD = v->y;
    }
    ull wpB = pk2(wpv.y, wpv.y), wpC = pk2(wpv.z, wpv.z);
    ull wmB = pk2(wmv.y, wmv.y), wmC = pk2(wmv.z, wmv.z);
#pragma unroll
    for (int bb = 0; bb < 4; bb++) {
        aP[bb][0] = ffma2(c0[bb].x, wpA, aP[bb][0]);
        aP[bb][1] = ffma2(c0[bb].y, wpB, aP[bb][1]);
        aP[bb][2] = ffma2(c1[bb].x, wpC, aP[bb][2]);
        aP[bb][3] = ffma2(c1[bb].y, wpD, aP[bb][3]);
        aM[bb][0] = ffma2(c0[bb].x, wmA, aM[bb][0]);
        aM[bb][1] = ffma2(c0[bb].y, wmB, aM[bb][1]);
        aM[bb][2] = ffma2(c1[bb].x, wmC, aM[bb][2]);
        aM[bb][3] = ffma2(c1[bb].y, wmD, aM[bb][3]);
    }
}

__global__ __launch_bounds__(THREADS, 1)
void clifford_gate_kernel(const float* __restrict__ x,
                          const float* __restrict__ wp,
                          const float* __restrict__ bpr,
                          const float* __restrict__ wm,
                          const float* __restrict__ bmr,
                          float* __restrict__ out,
                          int ntiles) {
    extern __shared__ float smf[];
    float4* wsp = reinterpret_cast<float4*>(smf);          // 4096 float4, [m*64+n]
    float4* wsm = wsp + 4096;                               // 4096 float4
    float*  xb  = smf + 32768;                              // 2 * 8192 floats

    const int tid  = threadIdx.x;
    const int lane = tid & 31;
    const int warp = tid >> 5;
    const int n    = ((warp & 1) << 5) | lane;   // 0..63
    const int bg4  = (warp >> 1) << 2;           // local b base: 0,4,8,12

    // ---- stage weights once: gmem [n][m][4] -> smem [m][n][4] ----
    {
        const float4* gp = reinterpret_cast<const float4*>(wp);
        const float4* gm = reinterpret_cast<const float4*>(wm);
        for (int idx = tid; idx < 4096; idx += THREADS) {
            int nn = idx & 63, mm = idx >> 6;
            wsp[mm * 64 + nn] = gp[nn * 64 + mm];
            wsm[mm * 64 + nn] = gm[nn * 64 + mm];
        }
    }
    const float biasp = bpr[n];
    const float biasm = bmr[n];

    int t = blockIdx.x;
    const int stride = gridDim.x;
    if (t < ntiles) stage_tile(x, xb, t, tid);
    asm volatile("cp.async.wait_group 0;\n");
    __syncthreads();

    int cur = 0;
    const float s2 = 0.70710678118654752440f;

    for (; t < ntiles; t += stride) {
        int tn = t + stride;
        if (tn < ntiles) stage_tile(x, xb + (cur ^ 1) * 8192, tn, tid);

        ull aP[4][4], aM[4][4];
#pragma unroll
        for (int i = 0; i < 4; i++)
#pragma unroll
            for (int j = 0; j < 4; j++) { aP[i][j] = 0ull; aM[i][j] = 0ull; }

        const float* xbc = xb + cur * 8192;

        // ---- software-pipelined mainloop: prefetch depth 1 m, ping-pong ----
        float4 wpA4, wmA4, wpB4, wmB4;
        ulonglong2 a0[4], a1[4], b0[4], b1[4];

        ldw(wsp, wsm, 0, n, wpA4, wmA4);
        ldx(xbc, bg4, 0, a0, a1);

#pragma unroll 4
        for (int m = 0; m < 64; m += 2) {
            // prefetch m+1 into set B, then consume set A (m)
            ldw(wsp, wsm, m + 1, n, wpB4, wmB4);
            ldx(xbc, bg4, m + 1, b0, b1);
            domma(wpA4, wmA4, a0, a1, aP, aM);
            // prefetch m+2 (wraps to 0 on last block; loaded value unused)
            int m2 = (m + 2) & 63;
            ldw(wsp, wsm, m2, n, wpA4, wmA4);
            ldx(xbc, bg4, m2, a0, a1);
            domma(wpB4, wmB4, b0, b1, aP, aM);
        }

        // ---------------- epilogue ----------------
        size_t bbase = (size_t)t * TB + bg4;
#pragma unroll
        for (int bb = 0; bb < 4; bb++) {
            float p0, p1, p2, p3, p4, p5, p6, p7;
            float m0, m1, m2, m3, m4, m5, m6, m7;
            unpk(aP[bb][0], p0, p1); unpk(aP[bb][1], p2, p3);
            unpk(aP[bb][2], p4, p5); unpk(aP[bb][3], p6, p7);
            unpk(aM[bb][0], m0, m1); unpk(aM[bb][1], m2, m3);
            unpk(aM[bb][2], m4, m5); unpk(aM[bb][3], m6, m7);
            p0 = __fadd_rn(p0, biasp);
            m0 = __fadd_rn(m0, biasm);

            // gate: individually rounded multiplies + sequential adds i=0..7.
            // NO FMA here (bit-exactness near b==0 is required).
            float bgv;
            bgv = __fmul_rn(p0, m0);
            bgv = __fadd_rn(bgv, __fmul_rn(p1, m1));
            bgv = __fadd_rn(bgv, __fmul_rn(p2, m2));
            bgv = __fadd_rn(bgv, __fmul_rn(p3, m3));
            bgv = __fadd_rn(bgv, __fmul_rn(p4, m4));
            bgv = __fadd_rn(bgv, __fmul_rn(p5, m5));
            bgv = __fadd_rn(bgv, __fmul_rn(p6, m6));
            bgv = __fadd_rn(bgv, __fmul_rn(p7, m7));

            // q: same rounding discipline (singular near q==0).
            float qv;
            qv = __fmul_rn(m0, m0);
            qv = __fadd_rn(qv, __fmul_rn(m1, m1));
            qv = __fadd_rn(qv, __fmul_rn(m2, m2));
            qv = __fadd_rn(qv, __fmul_rn(m3, m3));
            qv = __fadd_rn(qv, -__fmul_rn(m4, m4));
            qv = __fadd_rn(qv, -__fmul_rn(m5, m5));
            qv = __fadd_rn(qv, -__fmul_rn(m6, m6));
            qv = __fadd_rn(qv, -__fmul_rn(m7, m7));

            float qs  = __fadd_rn(__fmul_rn(qv, qv), 1e-16f);
            float nrm = __fsqrt_rn(__fsqrt_rn(qs));
            float inv = __frcp_rn(nrm);

            float n0 = m0 * inv, n1 = m1 * inv, n2 = m2 * inv, n3 = m3 * inv;
            float n4 = m4 * inv, n5 = m5 * inv, n6 = m6 * inv, n7 = m7 * inv;

            // Cl(3,0) geometric product r = p * n (well-conditioned; fma ok)
            float r0 = p0*n0 + p1*n1 + p2*n2 + p3*n3 - p4*n4 - p5*n5 - p6*n6 - p7*n7;
            float r1 = p0*n1 + p1*n0 - p2*n4 + p4*n2 - p3*n5 + p5*n3 - p6*n7 - p7*n6;
            float r2 = p0*n2 + p2*n0 + p1*n4 - p4*n1 - p3*n6 + p6*n3 + p5*n7 + p7*n5;
            float r3 = p0*n3 + p3*n0 + p1*n5 - p5*n1 + p2*n6 - p6*n2 - p4*n7 - p7*n4;
            float r4 = p0*n4 + p4*n0 + p1*n2 - p2*n1 + p3*n7 + p7*n3 - p5*n6 + p6*n5;
            float r5 = p0*n5 + p5*n0 + p1*n3 - p3*n1 - p2*n7 - p7*n2 + p4*n6 - p6*n4;
            float r6 = p0*n6 + p6*n0 + p1*n7 + p7*n1 + p2*n3 - p3*n2 - p4*n5 + p5*n4;
            float r7 = p0*n7 + p7*n0 + p1*n6 + p6*n1 - p2*n5 - p5*n2 + p3*n4 + p4*n3;

            bool sel = bgv > 0.0f;
            float4 o0, o1;
            o0.x = (sel ? p0 : r0) * s2;
            o0.y = (sel ? p1 : r1) * s2;
            o0.z = (sel ? p2 : r2) * s2;
            o0.w = (sel ? p3 : r3) * s2;
            o1.x = (sel ? p4 : r4) * s2;
            o1.y = (sel ? p5 : r5) * s2;
            o1.z = (sel ? p6 : r6) * s2;
            o1.w = (sel ? p7 : r7) * s2;

            float4* op = reinterpret_cast<float4*>(
                out + (((bbase + bb) << 6) + n) * 8);
            op[0] = o0;
            op[1] = o1;
        }

        asm volatile("cp.async.wait_group 0;\n");
        __syncthreads();
        cur ^= 1;
    }
}

extern "C" void kernel_launch(void* const* d_in, const int* in_sizes, int n_in,
                              void* d_out, int out_size) {
    const float* x   = (const float*)d_in[0];
    const float* wp  = (const float*)d_in[1];
    const float* bpr = (const float*)d_in[2];
    const float* wm  = (const float*)d_in[3];
    const float* bmr = (const float*)d_in[4];
    float* out = (float*)d_out;

    int B = in_sizes[0] / 512;      // x is (B, 64, 8)
    int ntiles = B / TB;

    cudaFuncSetAttribute(clifford_gate_kernel,
                         cudaFuncAttributeMaxDynamicSharedMemorySize, SMEM_BYTES);

    int dev = 0, sms = 148;
    cudaGetDevice(&dev);
    cudaDeviceGetAttribute(&sms, cudaDevAttrMultiProcessorCount, dev);
    int grid = sms < ntiles ? sms : ntiles;
    if (grid < 1) grid = 1;

    clifford_gate_kernel<<<grid, THREADS, SMEM_BYTES>>>(
        x, wp, bpr, wm, bmr, out, ntiles);
}